// round 12
// baseline (speedup 1.0000x reference)
#include <cuda_runtime.h>
#include <cuda_fp16.h>
#include <math.h>
#include <stdint.h>

#define N_TOT 8192
#define D     128
#define G     64        // 64 row-groups of 128 rows
#define NTRI  2080      // 64 diag + 2016 upper off-diag tiles
#define NBLK  296       // 2 CTAs per SM

__device__ __align__(16) __half g_h[N_TOT * D];   // fp16 normalized features
__device__ float g_acc[G * G * 128];              // per-(target,other) group partials
__device__ float g_pos[N_TOT];
__device__ float g_grpsum[G];                     // per-group loss sums
__device__ unsigned int g_ctrI[G];                // monotonic; +64 per launch each
__device__ unsigned int g_done;                   // monotonic; +64 per launch

// dynamic smem offsets (single-buffered tile pair -> 2 CTAs/SM)
#define OFF_A  0
#define OFF_B  32768
#define OFF_RP 65536                     // 128*2 floats
#define OFF_CP (OFF_RP + 1024)           // 128*4 floats
#define SMEM_DYN (OFF_CP + 2048)         // 68608 B

__device__ __forceinline__ float fast_exp2(float x) {
    float y;
    asm("ex2.approx.ftz.f32 %0, %1;" : "=f"(y) : "f"(x));
    return y;
}

// XOR-swizzled 256B-pitch tile offset (row r 0..127, 16B chunk ck 0..15)
__device__ __forceinline__ uint32_t sw(int r, int ck) {
    return (uint32_t)(r * 256 + ((ck ^ (r & 7)) << 4));
}

__device__ __forceinline__ void ldmatrix_x4(uint32_t& r0, uint32_t& r1,
                                            uint32_t& r2, uint32_t& r3,
                                            uint32_t addr) {
    asm volatile("ldmatrix.sync.aligned.m8n8.x4.shared.b16 {%0,%1,%2,%3}, [%4];"
                 : "=r"(r0), "=r"(r1), "=r"(r2), "=r"(r3) : "r"(addr) : "memory");
}

__device__ __forceinline__ void mma_f16(float c[4],
                                        uint32_t a0, uint32_t a1, uint32_t a2, uint32_t a3,
                                        uint32_t b0, uint32_t b1) {
    asm volatile("mma.sync.aligned.m16n8k16.row.col.f32.f16.f16.f32 "
                 "{%0,%1,%2,%3},{%4,%5,%6,%7},{%8,%9},{%0,%1,%2,%3};"
                 : "+f"(c[0]), "+f"(c[1]), "+f"(c[2]), "+f"(c[3])
                 : "r"(a0), "r"(a1), "r"(a2), "r"(a3), "r"(b0), "r"(b1));
}

#define CP16(dst, src) \
    asm volatile("cp.async.cg.shared.global [%0], [%1], 16;" :: "r"(dst), "l"(src))

__device__ __forceinline__ void decode_tile(int t, int& I, int& J) {
    int i = 0;
    while (t >= G - i) { t -= G - i; i++; }
    I = i; J = i + t;
}

// ---------------------------------------------------------------------------
// Kernel 1: L2-normalize each row, emit fp16 (one warp per row)  [R8 version]
// ---------------------------------------------------------------------------
__global__ void normalize_kernel(const float* __restrict__ in) {
    int warp = (blockIdx.x * blockDim.x + threadIdx.x) >> 5;
    int lane = threadIdx.x & 31;
    if (warp >= N_TOT) return;
    float4 v = reinterpret_cast<const float4*>(in + warp * D)[lane];
    float ss = v.x * v.x + v.y * v.y + v.z * v.z + v.w * v.w;
    #pragma unroll
    for (int o = 16; o > 0; o >>= 1)
        ss += __shfl_xor_sync(0xffffffffu, ss, o);
    float scale = 1.0f / fmaxf(sqrtf(ss), 1e-12f);
    __half2 h0 = __floats2half2_rn(v.x * scale, v.y * scale);
    __half2 h1 = __floats2half2_rn(v.z * scale, v.w * scale);
    uint2 pk;
    pk.x = *reinterpret_cast<uint32_t*>(&h0);
    pk.y = *reinterpret_cast<uint32_t*>(&h1);
    reinterpret_cast<uint2*>(g_h + warp * D)[lane] = pk;
}

// ---------------------------------------------------------------------------
// Kernel 2: symmetric persistent fp16 mma.sync sim-GEMM (R8 body) with a
// DEFERRED event-driven tail: thread 0 bumps per-group counters per tile and
// records completed groups; reductions + output happen AFTER the tile loop.
// ---------------------------------------------------------------------------
__global__ void __launch_bounds__(256, 2) simloss_kernel(
        float* __restrict__ out, int out_size) {
    extern __shared__ char smem[];
    const uint32_t sb = (uint32_t)__cvta_generic_to_shared(smem);
    float* rp2 = reinterpret_cast<float*>(smem + OFF_RP);   // [128][2] by wn
    float* cp2 = reinterpret_cast<float*>(smem + OFF_CP);   // [128][4] by wm
    __shared__ int hitList[16];
    __shared__ int hitCnt;

    const int t    = threadIdx.x;
    const int lane = t & 31;
    const int w    = t >> 5;
    const int wm   = w & 3;
    const int wn   = w >> 2;
    const int g    = lane >> 2;
    const int tg   = lane & 3;

    if (t == 0) hitCnt = 0;

    const int ld_r = t >> 4, ld_ck = t & 15;
    auto stage = [&](int I, int J) {
        const __half* srcA = g_h + (size_t)(I * 128) * D;
        const __half* srcB = g_h + (size_t)(J * 128) * D;
        #pragma unroll
        for (int j = 0; j < 8; j++) {
            int r = ld_r + j * 16;
            CP16(sb + OFF_A + sw(r, ld_ck), srcA + r * D + ld_ck * 8);
        }
        #pragma unroll
        for (int j = 0; j < 8; j++) {
            int r = ld_r + j * 16;
            CP16(sb + OFF_B + sw(r, ld_ck), srcB + r * D + ld_ck * 8);
        }
        asm volatile("cp.async.commit_group;" ::: "memory");
    };

    const int laneLo = lane & 15;
    const int hiA    = lane >> 4;
    const int rbL    = (lane & 7) + ((lane >> 4) << 3);
    const int ckBbit = (lane >> 3) & 1;

    const float invT = 14.285714285714286f;
    const float CEXP = 20.609929869842332f;   // log2(e)/0.07

    for (int tcur = blockIdx.x; tcur < NTRI; tcur += NBLK) {
        int I, J;
        decode_tile(tcur, I, J);
        stage(I, J);
        asm volatile("cp.async.wait_group 0;" ::: "memory");
        __syncthreads();   // tile staged; prev write-out done before rp2/cp2 reuse

        const uint32_t Ab = sb + OFF_A;
        const uint32_t Bb = sb + OFF_B;

        float c[2][8][4];
        #pragma unroll
        for (int mt = 0; mt < 2; mt++)
            #pragma unroll
            for (int nt = 0; nt < 8; nt++)
                c[mt][nt][0] = c[mt][nt][1] = c[mt][nt][2] = c[mt][nt][3] = 0.0f;

        #pragma unroll
        for (int kk = 0; kk < 8; kk++) {
            uint32_t aF[2][4];
            #pragma unroll
            for (int mt = 0; mt < 2; mt++) {
                const int rowA = wm * 32 + mt * 16 + laneLo;
                const int ckA  = kk * 2 + hiA;
                ldmatrix_x4(aF[mt][0], aF[mt][1], aF[mt][2], aF[mt][3],
                            Ab + rowA * 256 + ((ckA ^ (rowA & 7)) << 4));
            }
            const int ckB = kk * 2 + ckBbit;
            #pragma unroll
            for (int p = 0; p < 4; p++) {
                const int rowB = wn * 64 + p * 16 + rbL;
                uint32_t b0, b1, b2, b3;
                ldmatrix_x4(b0, b1, b2, b3,
                            Bb + rowB * 256 + ((ckB ^ (rowB & 7)) << 4));
                #pragma unroll
                for (int mt = 0; mt < 2; mt++) {
                    mma_f16(c[mt][2 * p],     aF[mt][0], aF[mt][1], aF[mt][2], aF[mt][3], b0, b1);
                    mma_f16(c[mt][2 * p + 1], aF[mt][0], aF[mt][1], aF[mt][2], aF[mt][3], b2, b3);
                }
            }
        }

        // ---- epilogue ----
        const bool isDiag = (I == J);
        const bool isPos  = (J == I + 32);

        float rs[2][2] = {{0.f, 0.f}, {0.f, 0.f}};   // [mt][g-half]
        float cs0[8], cs1[8];
        #pragma unroll
        for (int nt = 0; nt < 8; nt++) { cs0[nt] = 0.f; cs1[nt] = 0.f; }

        #pragma unroll
        for (int mt = 0; mt < 2; mt++) {
            const int lr0 = wm * 32 + mt * 16 + g;
            const int lr1 = lr0 + 8;
            #pragma unroll
            for (int nt = 0; nt < 8; nt++) {
                const int lc0 = wn * 64 + nt * 8 + tg * 2;
                const int lc1 = lc0 + 1;
                float v0 = c[mt][nt][0], v1 = c[mt][nt][1];
                float v2 = c[mt][nt][2], v3 = c[mt][nt][3];
                float e0 = fast_exp2(v0 * CEXP), e1 = fast_exp2(v1 * CEXP);
                float e2 = fast_exp2(v2 * CEXP), e3 = fast_exp2(v3 * CEXP);
                if (isDiag) {
                    if (lr0 == lc0) e0 = 0.f;
                    if (lr0 == lc1) e1 = 0.f;
                    if (lr1 == lc0) e2 = 0.f;
                    if (lr1 == lc1) e3 = 0.f;
                } else if (isPos) {
                    if (lr0 == lc0) { float pv = v0 * invT; int i0 = I * 128 + lr0; g_pos[i0] = pv; g_pos[i0 + 4096] = pv; }
                    if (lr0 == lc1) { float pv = v1 * invT; int i0 = I * 128 + lr0; g_pos[i0] = pv; g_pos[i0 + 4096] = pv; }
                    if (lr1 == lc0) { float pv = v2 * invT; int i0 = I * 128 + lr1; g_pos[i0] = pv; g_pos[i0 + 4096] = pv; }
                    if (lr1 == lc1) { float pv = v3 * invT; int i0 = I * 128 + lr1; g_pos[i0] = pv; g_pos[i0 + 4096] = pv; }
                }
                rs[mt][0] += e0 + e1;
                rs[mt][1] += e2 + e3;
                cs0[nt] += e0 + e2;
                cs1[nt] += e1 + e3;
            }
        }

        // reduce row-sums over tg (4 lanes per row)
        #pragma unroll
        for (int mt = 0; mt < 2; mt++) {
            #pragma unroll
            for (int h = 0; h < 2; h++) {
                float v = rs[mt][h];
                v += __shfl_xor_sync(0xffffffffu, v, 1);
                v += __shfl_xor_sync(0xffffffffu, v, 2);
                rs[mt][h] = v;
            }
        }
        if (tg == 0) {
            #pragma unroll
            for (int mt = 0; mt < 2; mt++) {
                rp2[(wm * 32 + mt * 16 + g) * 2 + wn]     = rs[mt][0];
                rp2[(wm * 32 + mt * 16 + g + 8) * 2 + wn] = rs[mt][1];
            }
        }

        // reduce col-sums over g (8 lanes per col pair)
        #pragma unroll
        for (int nt = 0; nt < 8; nt++) {
            float v0 = cs0[nt], v1 = cs1[nt];
            #pragma unroll
            for (int o = 4; o <= 16; o <<= 1) {
                v0 += __shfl_xor_sync(0xffffffffu, v0, o);
                v1 += __shfl_xor_sync(0xffffffffu, v1, o);
            }
            cs0[nt] = v0; cs1[nt] = v1;
        }
        if (lane < 4) {
            #pragma unroll
            for (int nt = 0; nt < 8; nt++) {
                const int col = wn * 64 + nt * 8 + lane * 2;
                cp2[col * 4 + wm]       = cs0[nt];
                cp2[(col + 1) * 4 + wm] = cs1[nt];
            }
        }
        __syncthreads();   // all MMA reads + rp2/cp2 writes done

        if (t < 128) {
            float rv = rp2[t * 2] + rp2[t * 2 + 1];
            g_acc[(I * G + J) * 128 + t] = rv;
            if (!isDiag) {
                float cv = cp2[t * 4] + cp2[t * 4 + 1] + cp2[t * 4 + 2] + cp2[t * 4 + 3];
                g_acc[(J * G + I) * 128 + t] = cv;
            }
        }
        __syncthreads();   // g_acc writes ordered before counter bump

        // ---- minimal in-loop bookkeeping (thread 0 only; deferred work) ----
        if (t == 0) {
            __threadfence();   // publish this tile's g_acc/g_pos
            unsigned int o1 = atomicAdd(&g_ctrI[I], 1u);
            if ((o1 & 63u) == 63u) hitList[hitCnt++] = I;
            if (!isDiag) {
                unsigned int o2 = atomicAdd(&g_ctrI[J], 1u);
                if ((o2 & 63u) == 63u) hitList[hitCnt++] = J;
            }
        }
        // next iteration's post-stage __syncthreads orders everything for reuse
    }
    __syncthreads();   // hitList/hitCnt visible to all threads

    // ---- deferred tail: reduce completed groups; last one writes output ----
    const int nHits = hitCnt;
    for (int hx = 0; hx < nHits; hx++) {
        const int gi = hitList[hx];
        __threadfence();   // acquire all 64 contributors' g_acc/g_pos writes
        if (t < 128) {
            float s = 0.0f;
            #pragma unroll 8
            for (int O = 0; O < G; O++) s += g_acc[(gi * G + O) * 128 + t];
            rp2[t] = logf(s) - g_pos[gi * 128 + t];
        }
        __syncthreads();
        #pragma unroll
        for (int o = 64; o > 0; o >>= 1) {
            if (t < o) rp2[t] += rp2[t + o];
            __syncthreads();
        }
        if (t == 0) {
            g_grpsum[gi] = rp2[0];
            __threadfence();
            unsigned int od = atomicAdd(&g_done, 1u);
            if ((od & 63u) == 63u) {
                __threadfence();
                float tot = 0.0f;
                #pragma unroll 8
                for (int k = 0; k < G; k++) tot += g_grpsum[k];
                const float mean = tot * (1.0f / (float)N_TOT);
                for (int k = 0; k < out_size; k++) out[k] = mean;
            }
        }
        __syncthreads();
    }
}

extern "C" void kernel_launch(void* const* d_in, const int* in_sizes, int n_in,
                              void* d_out, int out_size) {
    (void)in_sizes; (void)n_in;
    const float* features = (const float*)d_in[0];
    float* out = (float*)d_out;

    cudaFuncSetAttribute(simloss_kernel,
                         cudaFuncAttributeMaxDynamicSharedMemorySize, SMEM_DYN);

    normalize_kernel<<<N_TOT / 8, 256>>>(features);
    simloss_kernel<<<NBLK, 256, SMEM_DYN>>>(out, out_size);
}

// round 13
// speedup vs baseline: 1.7742x; 1.7742x over previous
#include <cuda_runtime.h>
#include <cuda_fp16.h>
#include <math.h>
#include <stdint.h>

#define N_TOT 8192
#define D     128
#define G     64        // 64 row-groups of 128 rows
#define NTRI  2080      // 64 diag + 2016 upper off-diag tiles
#define NBLK  296       // 2 CTAs per SM

__device__ __align__(16) __half g_h[N_TOT * D];   // fp16 normalized features
__device__ float g_acc[G * G * 128];              // per-(target,other) group partials
__device__ float g_pos[N_TOT];
__device__ float g_part[32];
__device__ unsigned int g_ctr;                    // monotonic; +32 per launch

// dynamic smem offsets (single-buffered tile pair -> 2 CTAs/SM)
#define OFF_A  0
#define OFF_B  32768
#define OFF_RP 65536                     // 128*2 floats
#define OFF_CP (OFF_RP + 1024)           // 128*4 floats
#define SMEM_DYN (OFF_CP + 2048)         // 68608 B

__device__ __forceinline__ float fast_exp2(float x) {
    float y;
    asm("ex2.approx.ftz.f32 %0, %1;" : "=f"(y) : "f"(x));
    return y;
}

// XOR-swizzled 256B-pitch tile offset (row r 0..127, 16B chunk ck 0..15)
__device__ __forceinline__ uint32_t sw(int r, int ck) {
    return (uint32_t)(r * 256 + ((ck ^ (r & 7)) << 4));
}

__device__ __forceinline__ void ldmatrix_x4(uint32_t& r0, uint32_t& r1,
                                            uint32_t& r2, uint32_t& r3,
                                            uint32_t addr) {
    asm volatile("ldmatrix.sync.aligned.m8n8.x4.shared.b16 {%0,%1,%2,%3}, [%4];"
                 : "=r"(r0), "=r"(r1), "=r"(r2), "=r"(r3) : "r"(addr) : "memory");
}

__device__ __forceinline__ void mma_f16(float c[4],
                                        uint32_t a0, uint32_t a1, uint32_t a2, uint32_t a3,
                                        uint32_t b0, uint32_t b1) {
    asm volatile("mma.sync.aligned.m16n8k16.row.col.f32.f16.f16.f32 "
                 "{%0,%1,%2,%3},{%4,%5,%6,%7},{%8,%9},{%0,%1,%2,%3};"
                 : "+f"(c[0]), "+f"(c[1]), "+f"(c[2]), "+f"(c[3])
                 : "r"(a0), "r"(a1), "r"(a2), "r"(a3), "r"(b0), "r"(b1));
}

#define CP16(dst, src) \
    asm volatile("cp.async.cg.shared.global [%0], [%1], 16;" :: "r"(dst), "l"(src))

__device__ __forceinline__ void decode_tile(int t, int& I, int& J) {
    int i = 0;
    while (t >= G - i) { t -= G - i; i++; }
    I = i; J = i + t;
}

// ---------------------------------------------------------------------------
// Kernel 1: L2-normalize, emit fp16; 2 rows per warp, both loads in flight
// (MLP=2) with grid 512 to keep occupancy high.
// ---------------------------------------------------------------------------
__global__ void normalize_kernel(const float* __restrict__ in) {
    const int warp = (blockIdx.x * blockDim.x + threadIdx.x) >> 5;
    const int lane = threadIdx.x & 31;
    const int r0 = warp * 2;
    if (r0 >= N_TOT) return;
    float4 v0 = reinterpret_cast<const float4*>(in + (size_t)r0 * D)[lane];
    float4 v1 = reinterpret_cast<const float4*>(in + (size_t)(r0 + 1) * D)[lane];

    float s0 = v0.x * v0.x + v0.y * v0.y + v0.z * v0.z + v0.w * v0.w;
    float s1 = v1.x * v1.x + v1.y * v1.y + v1.z * v1.z + v1.w * v1.w;
    #pragma unroll
    for (int o = 16; o > 0; o >>= 1) {
        s0 += __shfl_xor_sync(0xffffffffu, s0, o);
        s1 += __shfl_xor_sync(0xffffffffu, s1, o);
    }
    float sc0 = 1.0f / fmaxf(sqrtf(s0), 1e-12f);
    float sc1 = 1.0f / fmaxf(sqrtf(s1), 1e-12f);

    __half2 a0 = __floats2half2_rn(v0.x * sc0, v0.y * sc0);
    __half2 a1 = __floats2half2_rn(v0.z * sc0, v0.w * sc0);
    uint2 p0;
    p0.x = *reinterpret_cast<uint32_t*>(&a0);
    p0.y = *reinterpret_cast<uint32_t*>(&a1);
    reinterpret_cast<uint2*>(g_h + (size_t)r0 * D)[lane] = p0;

    __half2 b0 = __floats2half2_rn(v1.x * sc1, v1.y * sc1);
    __half2 b1 = __floats2half2_rn(v1.z * sc1, v1.w * sc1);
    uint2 p1;
    p1.x = *reinterpret_cast<uint32_t*>(&b0);
    p1.y = *reinterpret_cast<uint32_t*>(&b1);
    reinterpret_cast<uint2*>(g_h + (size_t)(r0 + 1) * D)[lane] = p1;
}

// ---------------------------------------------------------------------------
// Kernel 2: symmetric persistent fp16 mma.sync sim-GEMM; single-buffered,
// 2 CTAs/SM so one block's MMA overlaps the other's epilogue/staging.
// [R8 body, byte-identical]
// ---------------------------------------------------------------------------
__global__ void __launch_bounds__(256, 2) simloss_kernel() {
    extern __shared__ char smem[];
    const uint32_t sb = (uint32_t)__cvta_generic_to_shared(smem);
    float* rp2 = reinterpret_cast<float*>(smem + OFF_RP);   // [128][2] by wn
    float* cp2 = reinterpret_cast<float*>(smem + OFF_CP);   // [128][4] by wm

    const int t    = threadIdx.x;
    const int lane = t & 31;
    const int w    = t >> 5;
    const int wm   = w & 3;
    const int wn   = w >> 2;
    const int g    = lane >> 2;
    const int tg   = lane & 3;

    const int ld_r = t >> 4, ld_ck = t & 15;
    auto stage = [&](int I, int J) {
        const __half* srcA = g_h + (size_t)(I * 128) * D;
        const __half* srcB = g_h + (size_t)(J * 128) * D;
        #pragma unroll
        for (int j = 0; j < 8; j++) {
            int r = ld_r + j * 16;
            CP16(sb + OFF_A + sw(r, ld_ck), srcA + r * D + ld_ck * 8);
        }
        #pragma unroll
        for (int j = 0; j < 8; j++) {
            int r = ld_r + j * 16;
            CP16(sb + OFF_B + sw(r, ld_ck), srcB + r * D + ld_ck * 8);
        }
        asm volatile("cp.async.commit_group;" ::: "memory");
    };

    const int laneLo = lane & 15;
    const int hiA    = lane >> 4;
    const int rbL    = (lane & 7) + ((lane >> 4) << 3);
    const int ckBbit = (lane >> 3) & 1;

    const float invT = 14.285714285714286f;
    const float CEXP = 20.609929869842332f;   // log2(e)/0.07

    for (int tcur = blockIdx.x; tcur < NTRI; tcur += NBLK) {
        int I, J;
        decode_tile(tcur, I, J);
        stage(I, J);
        asm volatile("cp.async.wait_group 0;" ::: "memory");
        __syncthreads();   // tile staged; prev write-out done before rp2/cp2 reuse

        const uint32_t Ab = sb + OFF_A;
        const uint32_t Bb = sb + OFF_B;

        float c[2][8][4];
        #pragma unroll
        for (int mt = 0; mt < 2; mt++)
            #pragma unroll
            for (int nt = 0; nt < 8; nt++)
                c[mt][nt][0] = c[mt][nt][1] = c[mt][nt][2] = c[mt][nt][3] = 0.0f;

        #pragma unroll
        for (int kk = 0; kk < 8; kk++) {
            uint32_t aF[2][4];
            #pragma unroll
            for (int mt = 0; mt < 2; mt++) {
                const int rowA = wm * 32 + mt * 16 + laneLo;
                const int ckA  = kk * 2 + hiA;
                ldmatrix_x4(aF[mt][0], aF[mt][1], aF[mt][2], aF[mt][3],
                            Ab + rowA * 256 + ((ckA ^ (rowA & 7)) << 4));
            }
            const int ckB = kk * 2 + ckBbit;
            #pragma unroll
            for (int p = 0; p < 4; p++) {
                const int rowB = wn * 64 + p * 16 + rbL;
                uint32_t b0, b1, b2, b3;
                ldmatrix_x4(b0, b1, b2, b3,
                            Bb + rowB * 256 + ((ckB ^ (rowB & 7)) << 4));
                #pragma unroll
                for (int mt = 0; mt < 2; mt++) {
                    mma_f16(c[mt][2 * p],     aF[mt][0], aF[mt][1], aF[mt][2], aF[mt][3], b0, b1);
                    mma_f16(c[mt][2 * p + 1], aF[mt][0], aF[mt][1], aF[mt][2], aF[mt][3], b2, b3);
                }
            }
        }

        // ---- epilogue ----
        const bool isDiag = (I == J);
        const bool isPos  = (J == I + 32);

        float rs[2][2] = {{0.f, 0.f}, {0.f, 0.f}};   // [mt][g-half]
        float cs0[8], cs1[8];
        #pragma unroll
        for (int nt = 0; nt < 8; nt++) { cs0[nt] = 0.f; cs1[nt] = 0.f; }

        #pragma unroll
        for (int mt = 0; mt < 2; mt++) {
            const int lr0 = wm * 32 + mt * 16 + g;
            const int lr1 = lr0 + 8;
            #pragma unroll
            for (int nt = 0; nt < 8; nt++) {
                const int lc0 = wn * 64 + nt * 8 + tg * 2;
                const int lc1 = lc0 + 1;
                float v0 = c[mt][nt][0], v1 = c[mt][nt][1];
                float v2 = c[mt][nt][2], v3 = c[mt][nt][3];
                float e0 = fast_exp2(v0 * CEXP), e1 = fast_exp2(v1 * CEXP);
                float e2 = fast_exp2(v2 * CEXP), e3 = fast_exp2(v3 * CEXP);
                if (isDiag) {
                    if (lr0 == lc0) e0 = 0.f;
                    if (lr0 == lc1) e1 = 0.f;
                    if (lr1 == lc0) e2 = 0.f;
                    if (lr1 == lc1) e3 = 0.f;
                } else if (isPos) {
                    if (lr0 == lc0) { float pv = v0 * invT; int i0 = I * 128 + lr0; g_pos[i0] = pv; g_pos[i0 + 4096] = pv; }
                    if (lr0 == lc1) { float pv = v1 * invT; int i0 = I * 128 + lr0; g_pos[i0] = pv; g_pos[i0 + 4096] = pv; }
                    if (lr1 == lc0) { float pv = v2 * invT; int i0 = I * 128 + lr1; g_pos[i0] = pv; g_pos[i0 + 4096] = pv; }
                    if (lr1 == lc1) { float pv = v3 * invT; int i0 = I * 128 + lr1; g_pos[i0] = pv; g_pos[i0 + 4096] = pv; }
                }
                rs[mt][0] += e0 + e1;
                rs[mt][1] += e2 + e3;
                cs0[nt] += e0 + e2;
                cs1[nt] += e1 + e3;
            }
        }

        // reduce row-sums over tg (4 lanes per row)
        #pragma unroll
        for (int mt = 0; mt < 2; mt++) {
            #pragma unroll
            for (int h = 0; h < 2; h++) {
                float v = rs[mt][h];
                v += __shfl_xor_sync(0xffffffffu, v, 1);
                v += __shfl_xor_sync(0xffffffffu, v, 2);
                rs[mt][h] = v;
            }
        }
        if (tg == 0) {
            #pragma unroll
            for (int mt = 0; mt < 2; mt++) {
                rp2[(wm * 32 + mt * 16 + g) * 2 + wn]     = rs[mt][0];
                rp2[(wm * 32 + mt * 16 + g + 8) * 2 + wn] = rs[mt][1];
            }
        }

        // reduce col-sums over g (8 lanes per col pair)
        #pragma unroll
        for (int nt = 0; nt < 8; nt++) {
            float v0 = cs0[nt], v1 = cs1[nt];
            #pragma unroll
            for (int o = 4; o <= 16; o <<= 1) {
                v0 += __shfl_xor_sync(0xffffffffu, v0, o);
                v1 += __shfl_xor_sync(0xffffffffu, v1, o);
            }
            cs0[nt] = v0; cs1[nt] = v1;
        }
        if (lane < 4) {
            #pragma unroll
            for (int nt = 0; nt < 8; nt++) {
                const int col = wn * 64 + nt * 8 + lane * 2;
                cp2[col * 4 + wm]       = cs0[nt];
                cp2[(col + 1) * 4 + wm] = cs1[nt];
            }
        }
        __syncthreads();   // all MMA reads + rp2/cp2 writes done

        if (t < 128) {
            float rv = rp2[t * 2] + rp2[t * 2 + 1];
            g_acc[(I * G + J) * 128 + t] = rv;
            if (!isDiag) {
                float cv = cp2[t * 4] + cp2[t * 4 + 1] + cp2[t * 4 + 2] + cp2[t * 4 + 3];
                g_acc[(J * G + I) * 128 + t] = cv;
            }
        }
        // next iteration's post-stage __syncthreads orders write-out vs reuse
    }
}

// ---------------------------------------------------------------------------
// Kernel 3: fused per-row loss + mean (last-block reduction, deterministic)
// [R8 body]
// ---------------------------------------------------------------------------
__global__ void loss_reduce_kernel(float* __restrict__ out, int out_size) {
    __shared__ float ssum[256];
    __shared__ bool isLast;
    const int i = blockIdx.x * 256 + threadIdx.x;
    const int I = i >> 7, r = i & 127;
    float s = 0.0f;
    #pragma unroll 8
    for (int O = 0; O < G; O++) s += g_acc[(I * G + O) * 128 + r];
    ssum[threadIdx.x] = logf(s) - g_pos[i];
    __syncthreads();
    #pragma unroll
    for (int o = 128; o > 0; o >>= 1) {
        if (threadIdx.x < o) ssum[threadIdx.x] += ssum[threadIdx.x + o];
        __syncthreads();
    }
    if (threadIdx.x == 0) {
        g_part[blockIdx.x] = ssum[0];
        __threadfence();
        unsigned int old = atomicAdd(&g_ctr, 1u);
        isLast = ((old & 31u) == 31u);         // monotonic: replay-safe
    }
    __syncthreads();
    if (isLast && threadIdx.x < 32) {
        __threadfence();
        float v = ((volatile float*)g_part)[threadIdx.x];
        #pragma unroll
        for (int o = 16; o > 0; o >>= 1)
            v += __shfl_down_sync(0xffffffffu, v, o);
        if (threadIdx.x == 0) {
            const float mean = v * (1.0f / (float)N_TOT);
            for (int k = 0; k < out_size; k++) out[k] = mean;
        }
    }
}

extern "C" void kernel_launch(void* const* d_in, const int* in_sizes, int n_in,
                              void* d_out, int out_size) {
    (void)in_sizes; (void)n_in;
    const float* features = (const float*)d_in[0];
    float* out = (float*)d_out;

    cudaFuncSetAttribute(simloss_kernel,
                         cudaFuncAttributeMaxDynamicSharedMemorySize, SMEM_DYN);

    normalize_kernel<<<N_TOT / 16, 256>>>(features);
    simloss_kernel<<<NBLK, 256, SMEM_DYN>>>();
    loss_reduce_kernel<<<N_TOT / 256, 256>>>(out, out_size);
}

// round 14
// speedup vs baseline: 1.7824x; 1.0046x over previous
#include <cuda_runtime.h>
#include <cuda_fp16.h>
#include <math.h>
#include <stdint.h>

#define N_TOT 8192
#define D     128
#define G     64        // 64 row-groups of 128 rows
#define NTRI  2080      // 64 diag + 2016 upper off-diag tiles
#define NBLK  296       // 2 CTAs per SM

__device__ __align__(16) __half g_h[N_TOT * D];   // fp16 normalized features
__device__ float g_acc[G * G * 128];              // per-(target,other) group partials
__device__ float g_pos[N_TOT];
__device__ float g_part[32];
__device__ unsigned int g_ctr;                    // monotonic; +32 per launch

// dynamic smem offsets (single-buffered tile pair -> 2 CTAs/SM)
#define OFF_A  0
#define OFF_B  32768
#define OFF_RP 65536                     // 128*2 floats
#define OFF_CP (OFF_RP + 1024)           // 128*4 floats
#define SMEM_DYN (OFF_CP + 2048)         // 68608 B

__device__ __forceinline__ float fast_exp2(float x) {
    float y;
    asm("ex2.approx.ftz.f32 %0, %1;" : "=f"(y) : "f"(x));
    return y;
}

// XOR-swizzled 256B-pitch tile offset (row r 0..127, 16B chunk ck 0..15)
__device__ __forceinline__ uint32_t sw(int r, int ck) {
    return (uint32_t)(r * 256 + ((ck ^ (r & 7)) << 4));
}

__device__ __forceinline__ void ldmatrix_x4(uint32_t& r0, uint32_t& r1,
                                            uint32_t& r2, uint32_t& r3,
                                            uint32_t addr) {
    asm volatile("ldmatrix.sync.aligned.m8n8.x4.shared.b16 {%0,%1,%2,%3}, [%4];"
                 : "=r"(r0), "=r"(r1), "=r"(r2), "=r"(r3) : "r"(addr) : "memory");
}

__device__ __forceinline__ void mma_f16(float c[4],
                                        uint32_t a0, uint32_t a1, uint32_t a2, uint32_t a3,
                                        uint32_t b0, uint32_t b1) {
    asm volatile("mma.sync.aligned.m16n8k16.row.col.f32.f16.f16.f32 "
                 "{%0,%1,%2,%3},{%4,%5,%6,%7},{%8,%9},{%0,%1,%2,%3};"
                 : "+f"(c[0]), "+f"(c[1]), "+f"(c[2]), "+f"(c[3])
                 : "r"(a0), "r"(a1), "r"(a2), "r"(a3), "r"(b0), "r"(b1));
}

#define CP16(dst, src) \
    asm volatile("cp.async.cg.shared.global [%0], [%1], 16;" :: "r"(dst), "l"(src))

__device__ __forceinline__ void decode_tile(int t, int& I, int& J) {
    int i = 0;
    while (t >= G - i) { t -= G - i; i++; }
    I = i; J = i + t;
}

// ---------------------------------------------------------------------------
// Kernel 1: L2-normalize, emit fp16; 2 rows per warp [R13 version]
// ---------------------------------------------------------------------------
__global__ void normalize_kernel(const float* __restrict__ in) {
    const int warp = (blockIdx.x * blockDim.x + threadIdx.x) >> 5;
    const int lane = threadIdx.x & 31;
    const int r0 = warp * 2;
    if (r0 >= N_TOT) return;
    float4 v0 = reinterpret_cast<const float4*>(in + (size_t)r0 * D)[lane];
    float4 v1 = reinterpret_cast<const float4*>(in + (size_t)(r0 + 1) * D)[lane];

    float s0 = v0.x * v0.x + v0.y * v0.y + v0.z * v0.z + v0.w * v0.w;
    float s1 = v1.x * v1.x + v1.y * v1.y + v1.z * v1.z + v1.w * v1.w;
    #pragma unroll
    for (int o = 16; o > 0; o >>= 1) {
        s0 += __shfl_xor_sync(0xffffffffu, s0, o);
        s1 += __shfl_xor_sync(0xffffffffu, s1, o);
    }
    float sc0 = 1.0f / fmaxf(sqrtf(s0), 1e-12f);
    float sc1 = 1.0f / fmaxf(sqrtf(s1), 1e-12f);

    __half2 a0 = __floats2half2_rn(v0.x * sc0, v0.y * sc0);
    __half2 a1 = __floats2half2_rn(v0.z * sc0, v0.w * sc0);
    uint2 p0;
    p0.x = *reinterpret_cast<uint32_t*>(&a0);
    p0.y = *reinterpret_cast<uint32_t*>(&a1);
    reinterpret_cast<uint2*>(g_h + (size_t)r0 * D)[lane] = p0;

    __half2 b0 = __floats2half2_rn(v1.x * sc1, v1.y * sc1);
    __half2 b1 = __floats2half2_rn(v1.z * sc1, v1.w * sc1);
    uint2 p1;
    p1.x = *reinterpret_cast<uint32_t*>(&b0);
    p1.y = *reinterpret_cast<uint32_t*>(&b1);
    reinterpret_cast<uint2*>(g_h + (size_t)(r0 + 1) * D)[lane] = p1;
}

// ---------------------------------------------------------------------------
// Kernel 2: symmetric persistent fp16 mma.sync sim-GEMM; single-buffered,
// 2 CTAs/SM. NEW: next tile's cp.async issued right after the MMA loop so it
// fills during the epilogue (intra-block prefetch, same buffer).
// ---------------------------------------------------------------------------
__global__ void __launch_bounds__(256, 2) simloss_kernel() {
    extern __shared__ char smem[];
    const uint32_t sb = (uint32_t)__cvta_generic_to_shared(smem);
    float* rp2 = reinterpret_cast<float*>(smem + OFF_RP);   // [128][2] by wn
    float* cp2 = reinterpret_cast<float*>(smem + OFF_CP);   // [128][4] by wm

    const int t    = threadIdx.x;
    const int lane = t & 31;
    const int w    = t >> 5;
    const int wm   = w & 3;
    const int wn   = w >> 2;
    const int g    = lane >> 2;
    const int tg   = lane & 3;

    const int ld_r = t >> 4, ld_ck = t & 15;
    auto stage = [&](int I, int J) {
        const __half* srcA = g_h + (size_t)(I * 128) * D;
        const __half* srcB = g_h + (size_t)(J * 128) * D;
        #pragma unroll
        for (int j = 0; j < 8; j++) {
            int r = ld_r + j * 16;
            CP16(sb + OFF_A + sw(r, ld_ck), srcA + r * D + ld_ck * 8);
        }
        #pragma unroll
        for (int j = 0; j < 8; j++) {
            int r = ld_r + j * 16;
            CP16(sb + OFF_B + sw(r, ld_ck), srcB + r * D + ld_ck * 8);
        }
        asm volatile("cp.async.commit_group;" ::: "memory");
    };

    const int laneLo = lane & 15;
    const int hiA    = lane >> 4;
    const int rbL    = (lane & 7) + ((lane >> 4) << 3);
    const int ckBbit = (lane >> 3) & 1;

    const float invT = 14.285714285714286f;
    const float CEXP = 20.609929869842332f;   // log2(e)/0.07

    int tcur = blockIdx.x;
    int I, J;
    decode_tile(tcur, I, J);
    stage(I, J);

    while (tcur < NTRI) {
        asm volatile("cp.async.wait_group 0;" ::: "memory");
        __syncthreads();   // tile staged; prev g_acc write-out done (rp2/cp2 reuse safe)

        const uint32_t Ab = sb + OFF_A;
        const uint32_t Bb = sb + OFF_B;

        float c[2][8][4];
        #pragma unroll
        for (int mt = 0; mt < 2; mt++)
            #pragma unroll
            for (int nt = 0; nt < 8; nt++)
                c[mt][nt][0] = c[mt][nt][1] = c[mt][nt][2] = c[mt][nt][3] = 0.0f;

        #pragma unroll
        for (int kk = 0; kk < 8; kk++) {
            uint32_t aF[2][4];
            #pragma unroll
            for (int mt = 0; mt < 2; mt++) {
                const int rowA = wm * 32 + mt * 16 + laneLo;
                const int ckA  = kk * 2 + hiA;
                ldmatrix_x4(aF[mt][0], aF[mt][1], aF[mt][2], aF[mt][3],
                            Ab + rowA * 256 + ((ckA ^ (rowA & 7)) << 4));
            }
            const int ckB = kk * 2 + ckBbit;
            #pragma unroll
            for (int p = 0; p < 4; p++) {
                const int rowB = wn * 64 + p * 16 + rbL;
                uint32_t b0, b1, b2, b3;
                ldmatrix_x4(b0, b1, b2, b3,
                            Bb + rowB * 256 + ((ckB ^ (rowB & 7)) << 4));
                #pragma unroll
                for (int mt = 0; mt < 2; mt++) {
                    mma_f16(c[mt][2 * p],     aF[mt][0], aF[mt][1], aF[mt][2], aF[mt][3], b0, b1);
                    mma_f16(c[mt][2 * p + 1], aF[mt][0], aF[mt][1], aF[mt][2], aF[mt][3], b2, b3);
                }
            }
        }
        __syncthreads();   // all warps done reading A/B -> safe to restage

        // ---- prefetch next tile during the epilogue ----
        const int tnext = tcur + NBLK;
        int nI = 0, nJ = 0;
        if (tnext < NTRI) {
            decode_tile(tnext, nI, nJ);
            stage(nI, nJ);
        }

        // ---- epilogue ----
        const bool isDiag = (I == J);
        const bool isPos  = (J == I + 32);

        float rs[2][2] = {{0.f, 0.f}, {0.f, 0.f}};   // [mt][g-half]
        float cs0[8], cs1[8];
        #pragma unroll
        for (int nt = 0; nt < 8; nt++) { cs0[nt] = 0.f; cs1[nt] = 0.f; }

        #pragma unroll
        for (int mt = 0; mt < 2; mt++) {
            const int lr0 = wm * 32 + mt * 16 + g;
            const int lr1 = lr0 + 8;
            #pragma unroll
            for (int nt = 0; nt < 8; nt++) {
                const int lc0 = wn * 64 + nt * 8 + tg * 2;
                const int lc1 = lc0 + 1;
                float v0 = c[mt][nt][0], v1 = c[mt][nt][1];
                float v2 = c[mt][nt][2], v3 = c[mt][nt][3];
                float e0 = fast_exp2(v0 * CEXP), e1 = fast_exp2(v1 * CEXP);
                float e2 = fast_exp2(v2 * CEXP), e3 = fast_exp2(v3 * CEXP);
                if (isDiag) {
                    if (lr0 == lc0) e0 = 0.f;
                    if (lr0 == lc1) e1 = 0.f;
                    if (lr1 == lc0) e2 = 0.f;
                    if (lr1 == lc1) e3 = 0.f;
                } else if (isPos) {
                    if (lr0 == lc0) { float pv = v0 * invT; int i0 = I * 128 + lr0; g_pos[i0] = pv; g_pos[i0 + 4096] = pv; }
                    if (lr0 == lc1) { float pv = v1 * invT; int i0 = I * 128 + lr0; g_pos[i0] = pv; g_pos[i0 + 4096] = pv; }
                    if (lr1 == lc0) { float pv = v2 * invT; int i0 = I * 128 + lr1; g_pos[i0] = pv; g_pos[i0 + 4096] = pv; }
                    if (lr1 == lc1) { float pv = v3 * invT; int i0 = I * 128 + lr1; g_pos[i0] = pv; g_pos[i0 + 4096] = pv; }
                }
                rs[mt][0] += e0 + e1;
                rs[mt][1] += e2 + e3;
                cs0[nt] += e0 + e2;
                cs1[nt] += e1 + e3;
            }
        }

        // reduce row-sums over tg (4 lanes per row)
        #pragma unroll
        for (int mt = 0; mt < 2; mt++) {
            #pragma unroll
            for (int h = 0; h < 2; h++) {
                float v = rs[mt][h];
                v += __shfl_xor_sync(0xffffffffu, v, 1);
                v += __shfl_xor_sync(0xffffffffu, v, 2);
                rs[mt][h] = v;
            }
        }
        if (tg == 0) {
            #pragma unroll
            for (int mt = 0; mt < 2; mt++) {
                rp2[(wm * 32 + mt * 16 + g) * 2 + wn]     = rs[mt][0];
                rp2[(wm * 32 + mt * 16 + g + 8) * 2 + wn] = rs[mt][1];
            }
        }

        // reduce col-sums over g (8 lanes per col pair)
        #pragma unroll
        for (int nt = 0; nt < 8; nt++) {
            float v0 = cs0[nt], v1 = cs1[nt];
            #pragma unroll
            for (int o = 4; o <= 16; o <<= 1) {
                v0 += __shfl_xor_sync(0xffffffffu, v0, o);
                v1 += __shfl_xor_sync(0xffffffffu, v1, o);
            }
            cs0[nt] = v0; cs1[nt] = v1;
        }
        if (lane < 4) {
            #pragma unroll
            for (int nt = 0; nt < 8; nt++) {
                const int col = wn * 64 + nt * 8 + lane * 2;
                cp2[col * 4 + wm]       = cs0[nt];
                cp2[(col + 1) * 4 + wm] = cs1[nt];
            }
        }
        __syncthreads();   // rp2/cp2 writes done

        if (t < 128) {
            float rv = rp2[t * 2] + rp2[t * 2 + 1];
            g_acc[(I * G + J) * 128 + t] = rv;
            if (!isDiag) {
                float cv = cp2[t * 4] + cp2[t * 4 + 1] + cp2[t * 4 + 2] + cp2[t * 4 + 3];
                g_acc[(J * G + I) * 128 + t] = cv;
            }
        }

        tcur = tnext;
        I = nI; J = nJ;
        // loop-top wait+sync orders: staging complete, g_acc write-out done
    }
}

// ---------------------------------------------------------------------------
// Kernel 3: fused per-row loss + mean (last-block reduction, deterministic)
// ---------------------------------------------------------------------------
__global__ void loss_reduce_kernel(float* __restrict__ out, int out_size) {
    __shared__ float ssum[256];
    __shared__ bool isLast;
    const int i = blockIdx.x * 256 + threadIdx.x;
    const int I = i >> 7, r = i & 127;
    float s = 0.0f;
    #pragma unroll 8
    for (int O = 0; O < G; O++) s += g_acc[(I * G + O) * 128 + r];
    ssum[threadIdx.x] = logf(s) - g_pos[i];
    __syncthreads();
    #pragma unroll
    for (int o = 128; o > 0; o >>= 1) {
        if (threadIdx.x < o) ssum[threadIdx.x] += ssum[threadIdx.x + o];
        __syncthreads();
    }
    if (threadIdx.x == 0) {
        g_part[blockIdx.x] = ssum[0];
        __threadfence();
        unsigned int old = atomicAdd(&g_ctr, 1u);
        isLast = ((old & 31u) == 31u);         // monotonic: replay-safe
    }
    __syncthreads();
    if (isLast && threadIdx.x < 32) {
        __threadfence();
        float v = ((volatile float*)g_part)[threadIdx.x];
        #pragma unroll
        for (int o = 16; o > 0; o >>= 1)
            v += __shfl_down_sync(0xffffffffu, v, o);
        if (threadIdx.x == 0) {
            const float mean = v * (1.0f / (float)N_TOT);
            for (int k = 0; k < out_size; k++) out[k] = mean;
        }
    }
}

extern "C" void kernel_launch(void* const* d_in, const int* in_sizes, int n_in,
                              void* d_out, int out_size) {
    (void)in_sizes; (void)n_in;
    const float* features = (const float*)d_in[0];
    float* out = (float*)d_out;

    cudaFuncSetAttribute(simloss_kernel,
                         cudaFuncAttributeMaxDynamicSharedMemorySize, SMEM_DYN);

    normalize_kernel<<<N_TOT / 16, 256>>>(features);
    simloss_kernel<<<NBLK, 256, SMEM_DYN>>>();
    loss_reduce_kernel<<<N_TOT / 256, 256>>>(out, out_size);
}